// round 4
// baseline (speedup 1.0000x reference)
#include <cuda_runtime.h>
#include <cuda_bf16.h>
#include <cstdint>

// SparseDenseMatMul: out[M,64] = segment_sum(vals[:,None] * A[cols], rows)
// Inputs (metadata order): vals f32[NNZ], A f32[K,64], rows i32[NNZ], cols i32[NNZ]
// Output: f32[M*64]
//
// Strategy: 16 threads per nonzero edge; each thread handles 4 of the 64
// columns as a float4. Gather A[col] (L2-resident, 25.6MB < 126MB L2),
// scale, and scatter with a vector atomic red.global.add.v4.f32 (sm_90+).

#define N_COLS 64
#define VEC_PER_ROW (N_COLS / 4)   // 16 float4 lanes per row

__global__ __launch_bounds__(256) void spmm_coo_kernel(
    const float*  __restrict__ vals,
    const float*  __restrict__ A,
    const int*    __restrict__ rows,
    const int*    __restrict__ cols,
    float*        __restrict__ out,
    int nnz)
{
    // total threads = nnz * 16 = 25.6M < 2^31, 32-bit math is safe
    unsigned tid = blockIdx.x * blockDim.x + threadIdx.x;
    unsigned e = tid >> 4;       // edge index
    unsigned c = tid & 15u;      // which float4 of the 64-wide row
    if (e >= (unsigned)nnz) return;

    float v   = __ldg(&vals[e]);
    int   col = __ldg(&cols[e]);
    int   row = __ldg(&rows[e]);

    const float4* A4 = reinterpret_cast<const float4*>(A);
    float4 a = __ldg(&A4[(unsigned)col * VEC_PER_ROW + c]);

    float4 contrib;
    contrib.x = v * a.x;
    contrib.y = v * a.y;
    contrib.z = v * a.z;
    contrib.w = v * a.w;

    float4* o = reinterpret_cast<float4*>(out) + (unsigned)row * VEC_PER_ROW + c;

    // Vector atomic add (no return value) — sm_90+.
    asm volatile(
        "red.global.add.v4.f32 [%0], {%1, %2, %3, %4};"
        :: "l"(o), "f"(contrib.x), "f"(contrib.y), "f"(contrib.z), "f"(contrib.w)
        : "memory");
}

extern "C" void kernel_launch(void* const* d_in, const int* in_sizes, int n_in,
                              void* d_out, int out_size)
{
    const float* vals = (const float*)d_in[0];
    const float* A    = (const float*)d_in[1];
    const int*   rows = (const int*)d_in[2];
    const int*   cols = (const int*)d_in[3];
    float*       out  = (float*)d_out;

    int nnz = in_sizes[0];

    // d_out is poisoned to 0xAA — zero it first (memset node, graph-capturable).
    cudaMemsetAsync(out, 0, (size_t)out_size * sizeof(float));

    unsigned total_threads = (unsigned)nnz * VEC_PER_ROW;
    int block = 256;
    unsigned grid = (total_threads + block - 1) / block;

    spmm_coo_kernel<<<grid, block>>>(vals, A, rows, cols, out, nnz);
}